// round 10
// baseline (speedup 1.0000x reference)
#include <cuda_runtime.h>
#include <cstdint>

#define N_NODES   8192
#define THREADS   1024
#define GRID      152              // >= SM count; work-stealing tolerates fewer SMs
#define NBINS     256
#define CAND_MAX  1024
#define NGROUPS   64               // 16-lane group maxima (1024 thr / 16)
#define VEC_ITERS (N_NODES / 4 / THREADS)   // 2 float4 per thread
#define ROW_BYTES (N_NODES * 4)             // 32 KB
#define DYN_SMEM  (2 * 2 * N_NODES * 4)     // 128 KB: [buf][scores|noise][N]

__device__ unsigned g_row_ctr = 0;   // next row to process
__device__ unsigned g_done    = 0;   // finished-CTA count (for self-reset)

// Monotonic float -> uint mapping (larger float => larger uint). No NaNs in inputs.
__device__ __forceinline__ uint32_t f2ord(float f) {
    uint32_t u = __float_as_uint(f);
    return u ^ ((uint32_t)((int32_t)u >> 31) | 0x80000000u);
}

// Unique 48-bit total-order key: ties in value resolve to the smaller index
// (matching jax.lax.top_k).
__device__ __forceinline__ unsigned long long make_key(uint32_t ord, uint32_t j) {
    return ((unsigned long long)ord << 16) | (unsigned)(N_NODES - 1 - j);
}

__device__ __forceinline__ uint32_t smem_u32(const void* p) {
    return (uint32_t)__cvta_generic_to_shared(p);
}
__device__ __forceinline__ void mbar_init(uint32_t a, uint32_t cnt) {
    asm volatile("mbarrier.init.shared.b64 [%0], %1;" :: "r"(a), "r"(cnt) : "memory");
}
__device__ __forceinline__ void mbar_expect_tx(uint32_t a, uint32_t bytes) {
    asm volatile("mbarrier.arrive.expect_tx.shared.b64 _, [%0], %1;"
                 :: "r"(a), "r"(bytes) : "memory");
}
__device__ __forceinline__ void mbar_wait(uint32_t mbar, uint32_t parity) {
    uint32_t done;
    asm volatile(
        "{\n\t.reg .pred p;\n\t"
        "mbarrier.try_wait.parity.acquire.cta.shared::cta.b64 p, [%1], %2;\n\t"
        "selp.b32 %0, 1, 0, p;\n\t}"
        : "=r"(done) : "r"(mbar), "r"(parity) : "memory");
    if (!done) {
        asm volatile(
            "{\n\t.reg .pred P1;\n\t"
            "WAIT_LOOP_%=:\n\t"
            "mbarrier.try_wait.parity.acquire.cta.shared::cta.b64 P1, [%0], %1, 0x989680;\n\t"
            "@P1 bra.uni WAIT_DONE_%=;\n\t"
            "bra.uni WAIT_LOOP_%=;\n\t"
            "WAIT_DONE_%=:\n\t}"
            :: "r"(mbar), "r"(parity) : "memory");
    }
}
__device__ __forceinline__ void bulk_g2s(uint32_t dst, const void* src,
                                         uint32_t bytes, uint32_t mbar) {
    asm volatile(
        "cp.async.bulk.shared::cluster.global.mbarrier::complete_tx::bytes "
        "[%0], [%1], %2, [%3];"
        :: "r"(dst), "l"(src), "r"(bytes), "r"(mbar) : "memory");
}
__device__ __forceinline__ void fence_proxy_async_cta() {
    asm volatile("fence.proxy.async.shared::cta;" ::: "memory");
}

// Fallback-only: suffix-sum a 256-bin histogram, pick bin holding krem-th largest.
__device__ __forceinline__ void scan_pick(const uint32_t* hist,
                                          volatile uint32_t* s_cum,
                                          unsigned long long* s_prefix,
                                          int* s_krem)
{
    const int lane = threadIdx.x;           // caller guarantees tid < 32
    uint32_t h[8], suf[8];
    #pragma unroll
    for (int j = 0; j < 8; ++j) h[j] = hist[lane * 8 + j];
    uint32_t acc = 0;
    #pragma unroll
    for (int j = 7; j >= 0; --j) { acc += h[j]; suf[j] = acc; }
    uint32_t run = acc;
    #pragma unroll
    for (int off = 1; off < 32; off <<= 1) {
        uint32_t v = __shfl_down_sync(0xFFFFFFFFu, run, off);
        if (lane + off < 32) run += v;
    }
    const uint32_t above = run - acc;
    #pragma unroll
    for (int j = 0; j < 8; ++j) s_cum[lane * 8 + j] = above + suf[j];
    if (lane == 0) s_cum[NBINS] = 0;
    __syncwarp();
    const uint32_t krem = (uint32_t)(*s_krem);
    #pragma unroll
    for (int j = 0; j < 8; ++j) {
        const int b = lane * 8 + j;
        const uint32_t ge = s_cum[b];
        const uint32_t gt = s_cum[b + 1];
        if (ge >= krem && gt < krem) {
            *s_prefix = (*s_prefix << 8) | (unsigned long long)(uint32_t)b;
            *s_krem   = (int)(krem - gt);
        }
    }
}

extern __shared__ float sbuf[];   // [2][2][N_NODES]: buffer, scores|noise

__global__ __launch_bounds__(THREADS, 1)
void st_subset_sampler_kernel(const float* __restrict__ scores,
                              const float* __restrict__ noise,
                              const float* __restrict__ tau_p,
                              const int*   __restrict__ k_p,
                              float* __restrict__ out)
{
    __shared__ uint32_t s_gmax[NGROUPS];
    __shared__ unsigned long long s_ckey[CAND_MAX];   // 8 KB candidate keys
    __shared__ int      s_ncand;
    __shared__ uint32_t s_t32;
    __shared__ int      s_row[2];                     // row id per buffer
    __shared__ alignas(8) unsigned long long s_mb[2]; // mbarriers
    // fallback-only state
    __shared__ uint32_t s_hist[NBINS];
    __shared__ uint32_t s_cum[NBINS + 1];
    __shared__ unsigned long long s_prefix;
    __shared__ int      s_krem;

    const int tid = threadIdx.x;
    const float tau = __ldg(tau_p);
    const int   k   = __ldg(k_p);

    // Power-of-two tau => a/tau == a*(1/tau) exactly; mul-then-add matches the
    // reference rounding bit-for-bit. Otherwise exact fdiv fallback.
    const uint32_t tb = __float_as_uint(tau);
    const bool pow2 = ((tb & 0x007FFFFFu) == 0u) &&
                      ((tb & 0x7F800000u) != 0u) &&
                      ((tb & 0x7F800000u) != 0x7F800000u);
    const float rtau = __frcp_rn(tau);

    const uint32_t mb[2] = { smem_u32(&s_mb[0]), smem_u32(&s_mb[1]) };

    // ---- prologue: init barriers, steal first two rows, start both copies ----
    if (tid == 0) {
        mbar_init(mb[0], 1);
        mbar_init(mb[1], 1);
        fence_proxy_async_cta();              // init visible to async proxy
        s_row[0] = (int)atomicAdd(&g_row_ctr, 1u);
        s_row[1] = (int)atomicAdd(&g_row_ctr, 1u);
        #pragma unroll
        for (int b = 0; b < 2; ++b) {
            const int r = s_row[b];
            if (r < N_NODES) {
                float* bs = sbuf + (size_t)b * 2 * N_NODES;
                mbar_expect_tx(mb[b], 2 * ROW_BYTES);
                bulk_g2s(smem_u32(bs),            scores + (size_t)r * N_NODES, ROW_BYTES, mb[b]);
                bulk_g2s(smem_u32(bs + N_NODES),  noise  + (size_t)r * N_NODES, ROW_BYTES, mb[b]);
            }
        }
    }
    __syncthreads();

    int cur = 0;
    uint32_t par = 0;                          // parity bits per buffer
    for (;;) {
        const int rc = s_row[cur];             // valid: synced last iteration
        if (rc >= N_NODES) break;              // older slot exhausted => done
        const size_t row = (size_t)rc * N_NODES;

        mbar_wait(mb[cur], (par >> cur) & 1u); // background copy complete
        par ^= (1u << cur);
        if (tid == 0) { s_ncand = 0; s_t32 = 0; }

        float*    bs   = sbuf + (size_t)cur * 2 * N_NODES;
        float*    bn   = bs + N_NODES;
        uint32_t* ordp = reinterpret_cast<uint32_t*>(bs);   // ord overwrites scores

        // ---- phase 1: smem raw -> ord (in place), per-thread max ----
        uint32_t m = 0;
        if (pow2) {
            #pragma unroll
            for (int i = 0; i < VEC_ITERS; ++i) {
                const int idx = tid + i * THREADS;
                const float4 a = reinterpret_cast<const float4*>(bs)[idx];
                const float4 b = reinterpret_cast<const float4*>(bn)[idx];
                uint4 o;
                o.x = f2ord(__fadd_rn(__fmul_rn(a.x, rtau), b.x));
                o.y = f2ord(__fadd_rn(__fmul_rn(a.y, rtau), b.y));
                o.z = f2ord(__fadd_rn(__fmul_rn(a.z, rtau), b.z));
                o.w = f2ord(__fadd_rn(__fmul_rn(a.w, rtau), b.w));
                reinterpret_cast<uint4*>(ordp)[idx] = o;
                m = max(m, max(max(o.x, o.y), max(o.z, o.w)));
            }
        } else {
            #pragma unroll
            for (int i = 0; i < VEC_ITERS; ++i) {
                const int idx = tid + i * THREADS;
                const float4 a = reinterpret_cast<const float4*>(bs)[idx];
                const float4 b = reinterpret_cast<const float4*>(bn)[idx];
                uint4 o;
                o.x = f2ord(__fadd_rn(__fdiv_rn(a.x, tau), b.x));
                o.y = f2ord(__fadd_rn(__fdiv_rn(a.y, tau), b.y));
                o.z = f2ord(__fadd_rn(__fdiv_rn(a.z, tau), b.z));
                o.w = f2ord(__fadd_rn(__fdiv_rn(a.w, tau), b.w));
                reinterpret_cast<uint4*>(ordp)[idx] = o;
                m = max(m, max(max(o.x, o.y), max(o.z, o.w)));
            }
        }
        // 16-lane group max -> 64 group maxima
        #pragma unroll
        for (int off = 8; off > 0; off >>= 1)
            m = max(m, __shfl_down_sync(0xFFFFFFFFu, m, off, 16));
        if ((tid & 15) == 0) s_gmax[tid >> 4] = m;
        __syncthreads();

        // ---- phase 2: warp 0 exact-ranks the 64 group maxima ----
        // t32 = k-th largest group max <= true k-th largest element T
        // (the top-k group maxima are k distinct elements, each >= t32).
        if (tid < 32 && k >= 1 && k <= NGROUPS) {
            const uint32_t v0 = s_gmax[tid];
            const uint32_t v1 = s_gmax[tid + 32];
            int r0 = 0, r1 = 0;
            #pragma unroll 8
            for (int j = 0; j < NGROUPS; ++j) {
                const uint32_t w = s_gmax[j];
                r0 += (w > v0) || (w == v0 && j < tid);
                r1 += (w > v1) || (w == v1 && j < tid + 32);
            }
            if (r0 == k - 1) s_t32 = v0;
            if (r1 == k - 1) s_t32 = v1;
        }
        __syncthreads();
        const uint32_t t32 = s_t32;

        // ---- phase 3: fused provisional write + candidate compaction ----
        float4* op = reinterpret_cast<float4*>(out + row);
        #pragma unroll
        for (int i = 0; i < VEC_ITERS; ++i) {
            const int idx = tid + i * THREADS;
            const uint4 o = reinterpret_cast<const uint4*>(ordp)[idx];
            float4 r;
            r.x = (o.x >= t32) ? 1.0f : 0.0f;
            r.y = (o.y >= t32) ? 1.0f : 0.0f;
            r.z = (o.z >= t32) ? 1.0f : 0.0f;
            r.w = (o.w >= t32) ? 1.0f : 0.0f;
            __stcs(&op[idx], r);               // evict-first: pure write stream
            const uint32_t j = (uint32_t)idx * 4;
            if (o.x >= t32) { int p = atomicAdd(&s_ncand, 1); if (p < CAND_MAX) s_ckey[p] = make_key(o.x, j + 0); }
            if (o.y >= t32) { int p = atomicAdd(&s_ncand, 1); if (p < CAND_MAX) s_ckey[p] = make_key(o.y, j + 1); }
            if (o.z >= t32) { int p = atomicAdd(&s_ncand, 1); if (p < CAND_MAX) s_ckey[p] = make_key(o.z, j + 2); }
            if (o.w >= t32) { int p = atomicAdd(&s_ncand, 1); if (p < CAND_MAX) s_ckey[p] = make_key(o.w, j + 3); }
        }
        __syncthreads();
        const int nc = s_ncand;

        if (nc <= CAND_MAX) {
            // ---- phase 4: O(nc^2) exact rank over candidates (nc ~ k) ----
            // All true top-k have ord >= T >= t32, so they are candidates;
            // keys are unique, so (rank < k) selects exactly the global top-k.
            for (int c = tid; c < nc; c += THREADS) {
                const unsigned long long key = s_ckey[c];
                int rank = 0;
                for (int t = 0; t < nc; ++t)
                    rank += (s_ckey[t] > key);
                const uint32_t j = (uint32_t)(N_NODES - 1) - (uint32_t)(key & 0xFFFFu);
                out[row + j] = (rank < k) ? 1.0f : 0.0f;
            }
        } else {
            // ---- fallback (adversarial inputs only): exact 48-bit radix ----
            if (tid == 0) { s_prefix = 0ull; s_krem = k; }
            for (int d = 0; d < 6; ++d) {
                if (tid < NBINS) s_hist[tid] = 0;
                __syncthreads();
                const unsigned long long pre = s_prefix;
                const int shd = 40 - 8 * d, shp = 48 - 8 * d;
                for (int jj = tid; jj < N_NODES; jj += THREADS) {
                    const unsigned long long key = make_key(ordp[jj], (uint32_t)jj);
                    if (d == 0 || (key >> shp) == pre)
                        atomicAdd(&s_hist[(uint32_t)(key >> shd) & 0xFFu], 1u);
                }
                __syncthreads();
                if (tid < 32) scan_pick(s_hist, s_cum, &s_prefix, &s_krem);
                __syncthreads();
            }
            const unsigned long long thr = s_prefix;
            for (int jj = tid; jj < N_NODES; jj += THREADS)
                out[row + jj] = (make_key(ordp[jj], (uint32_t)jj) >= thr) ? 1.0f : 0.0f;
        }
        __syncthreads();       // all threads done reading buf[cur] / s_ckey

        // ---- refill buf[cur] with the next stolen row (streams in background) ----
        if (tid == 0) {
            const int rn = (int)atomicAdd(&g_row_ctr, 1u);
            s_row[cur] = rn;
            if (rn < N_NODES) {
                fence_proxy_async_cta();       // order generic STS before bulk WAW
                mbar_expect_tx(mb[cur], 2 * ROW_BYTES);
                bulk_g2s(smem_u32(bs), scores + (size_t)rn * N_NODES, ROW_BYTES, mb[cur]);
                bulk_g2s(smem_u32(bn), noise  + (size_t)rn * N_NODES, ROW_BYTES, mb[cur]);
            }
        }
        __syncthreads();       // publish s_row[cur] before next iteration reads it
        cur ^= 1;
    }

    // ---- self-reset of scheduler state for graph replay determinism ----
    __syncthreads();
    if (tid == 0) {
        __threadfence();
        if (atomicAdd(&g_done, 1u) == gridDim.x - 1) {  // last CTA; all ctr use done
            g_row_ctr = 0;
            __threadfence();
            atomicExch(&g_done, 0u);
        }
    }
}

extern "C" void kernel_launch(void* const* d_in, const int* in_sizes, int n_in,
                              void* d_out, int out_size) {
    (void)in_sizes; (void)n_in; (void)out_size;
    const float* scores = (const float*)d_in[0];
    const float* noise  = (const float*)d_in[1];
    const float* tau    = (const float*)d_in[2];
    const int*   k      = (const int*)d_in[3];
    float* out = (float*)d_out;
    cudaFuncSetAttribute(st_subset_sampler_kernel,
                         cudaFuncAttributeMaxDynamicSharedMemorySize, DYN_SMEM);
    st_subset_sampler_kernel<<<GRID, THREADS, DYN_SMEM>>>(scores, noise, tau, k, out);
}

// round 11
// speedup vs baseline: 1.3566x; 1.3566x over previous
#include <cuda_runtime.h>
#include <cstdint>

#define N_NODES   8192
#define THREADS   512
#define GRID      296              // 2 CTAs/SM on 148 SMs; static stripe
#define NBINS     256
#define CAND_MAX  512
#define NGROUPS   64               // 8-lane group maxima (512 thr / 8)
#define VEC_ITERS (N_NODES / 4 / THREADS)   // 4 float4 per thread
#define ROW_BYTES (N_NODES * 4)             // 32 KB per stream
#define DYN_SMEM  (3 * N_NODES * 4)         // 96 KB: staging(scores,noise) + ord

// Monotonic float -> uint mapping (larger float => larger uint). No NaNs in inputs.
__device__ __forceinline__ uint32_t f2ord(float f) {
    uint32_t u = __float_as_uint(f);
    return u ^ ((uint32_t)((int32_t)u >> 31) | 0x80000000u);
}

// Unique 48-bit total-order key: ties in value resolve to the smaller index
// (matching jax.lax.top_k).
__device__ __forceinline__ unsigned long long make_key(uint32_t ord, uint32_t j) {
    return ((unsigned long long)ord << 16) | (unsigned)(N_NODES - 1 - j);
}

__device__ __forceinline__ uint32_t smem_u32(const void* p) {
    return (uint32_t)__cvta_generic_to_shared(p);
}
__device__ __forceinline__ void mbar_init(uint32_t a, uint32_t cnt) {
    asm volatile("mbarrier.init.shared.b64 [%0], %1;" :: "r"(a), "r"(cnt) : "memory");
}
__device__ __forceinline__ void mbar_expect_tx(uint32_t a, uint32_t bytes) {
    asm volatile("mbarrier.arrive.expect_tx.shared.b64 _, [%0], %1;"
                 :: "r"(a), "r"(bytes) : "memory");
}
__device__ __forceinline__ void mbar_wait(uint32_t mbar, uint32_t parity) {
    uint32_t done;
    asm volatile(
        "{\n\t.reg .pred p;\n\t"
        "mbarrier.try_wait.parity.acquire.cta.shared::cta.b64 p, [%1], %2;\n\t"
        "selp.b32 %0, 1, 0, p;\n\t}"
        : "=r"(done) : "r"(mbar), "r"(parity) : "memory");
    if (!done) {
        asm volatile(
            "{\n\t.reg .pred P1;\n\t"
            "WAIT_LOOP_%=:\n\t"
            "mbarrier.try_wait.parity.acquire.cta.shared::cta.b64 P1, [%0], %1, 0x989680;\n\t"
            "@P1 bra.uni WAIT_DONE_%=;\n\t"
            "bra.uni WAIT_LOOP_%=;\n\t"
            "WAIT_DONE_%=:\n\t}"
            :: "r"(mbar), "r"(parity) : "memory");
    }
}
__device__ __forceinline__ void bulk_g2s(uint32_t dst, const void* src,
                                         uint32_t bytes, uint32_t mbar) {
    asm volatile(
        "cp.async.bulk.shared::cluster.global.mbarrier::complete_tx::bytes "
        "[%0], [%1], %2, [%3];"
        :: "r"(dst), "l"(src), "r"(bytes), "r"(mbar) : "memory");
}
__device__ __forceinline__ void fence_proxy_async_cta() {
    asm volatile("fence.proxy.async.shared::cta;" ::: "memory");
}

// Fallback-only: suffix-sum a 256-bin histogram, pick bin holding krem-th largest.
__device__ __forceinline__ void scan_pick(const uint32_t* hist,
                                          volatile uint32_t* s_cum,
                                          unsigned long long* s_prefix,
                                          int* s_krem)
{
    const int lane = threadIdx.x;           // caller guarantees tid < 32
    uint32_t h[8], suf[8];
    #pragma unroll
    for (int j = 0; j < 8; ++j) h[j] = hist[lane * 8 + j];
    uint32_t acc = 0;
    #pragma unroll
    for (int j = 7; j >= 0; --j) { acc += h[j]; suf[j] = acc; }
    uint32_t run = acc;
    #pragma unroll
    for (int off = 1; off < 32; off <<= 1) {
        uint32_t v = __shfl_down_sync(0xFFFFFFFFu, run, off);
        if (lane + off < 32) run += v;
    }
    const uint32_t above = run - acc;
    #pragma unroll
    for (int j = 0; j < 8; ++j) s_cum[lane * 8 + j] = above + suf[j];
    if (lane == 0) s_cum[NBINS] = 0;
    __syncwarp();
    const uint32_t krem = (uint32_t)(*s_krem);
    #pragma unroll
    for (int j = 0; j < 8; ++j) {
        const int b = lane * 8 + j;
        const uint32_t ge = s_cum[b];
        const uint32_t gt = s_cum[b + 1];
        if (ge >= krem && gt < krem) {
            *s_prefix = (*s_prefix << 8) | (unsigned long long)(uint32_t)b;
            *s_krem   = (int)(krem - gt);
        }
    }
}

extern __shared__ float sbuf[];   // [scores 8192 | noise 8192 | ord 8192(u32)]

__global__ __launch_bounds__(THREADS, 2)
void st_subset_sampler_kernel(const float* __restrict__ scores,
                              const float* __restrict__ noise,
                              const float* __restrict__ tau_p,
                              const int*   __restrict__ k_p,
                              float* __restrict__ out)
{
    __shared__ uint32_t s_gmax[NGROUPS];
    __shared__ unsigned long long s_ckey[CAND_MAX];   // 4 KB candidate keys
    __shared__ int      s_ncand;
    __shared__ uint32_t s_t32;
    __shared__ alignas(8) unsigned long long s_mb;    // TMA mbarrier
    // fallback-only state
    __shared__ uint32_t s_hist[NBINS];
    __shared__ uint32_t s_cum[NBINS + 1];
    __shared__ unsigned long long s_prefix;
    __shared__ int      s_krem;

    const int tid = threadIdx.x;
    const float tau = __ldg(tau_p);
    const int   k   = __ldg(k_p);

    // Power-of-two tau => a/tau == a*(1/tau) exactly; mul-then-add matches the
    // reference rounding bit-for-bit. Otherwise exact fdiv fallback.
    const uint32_t tb = __float_as_uint(tau);
    const bool pow2 = ((tb & 0x007FFFFFu) == 0u) &&
                      ((tb & 0x7F800000u) != 0u) &&
                      ((tb & 0x7F800000u) != 0x7F800000u);
    const float rtau = __frcp_rn(tau);

    float*    stg_s = sbuf;                 // TMA staging: raw scores
    float*    stg_n = sbuf + N_NODES;       // TMA staging: raw noise
    uint32_t* ordp  = reinterpret_cast<uint32_t*>(sbuf + 2 * N_NODES);
    const uint32_t mb = smem_u32(&s_mb);

    // ---- prologue: init barrier, start copy of this CTA's first row ----
    if (tid == 0) {
        mbar_init(mb, 1);
        fence_proxy_async_cta();            // init visible to async proxy
        mbar_expect_tx(mb, 2 * ROW_BYTES);
        bulk_g2s(smem_u32(stg_s), scores + (size_t)blockIdx.x * N_NODES, ROW_BYTES, mb);
        bulk_g2s(smem_u32(stg_n), noise  + (size_t)blockIdx.x * N_NODES, ROW_BYTES, mb);
    }
    __syncthreads();

    uint32_t par = 0;
    for (int row_i = blockIdx.x; row_i < N_NODES; row_i += GRID) {
        const size_t row = (size_t)row_i * N_NODES;

        // ---- wait for this row's background copy ----
        mbar_wait(mb, par);
        par ^= 1u;
        if (tid == 0) { s_ncand = 0; s_t32 = 0; }

        // ---- phase 1: convert staging -> ord (smem->smem), group maxima ----
        uint32_t m = 0;
        if (pow2) {
            #pragma unroll
            for (int i = 0; i < VEC_ITERS; ++i) {
                const int idx = tid + i * THREADS;
                const float4 a = reinterpret_cast<const float4*>(stg_s)[idx];
                const float4 b = reinterpret_cast<const float4*>(stg_n)[idx];
                uint4 o;
                o.x = f2ord(__fadd_rn(__fmul_rn(a.x, rtau), b.x));
                o.y = f2ord(__fadd_rn(__fmul_rn(a.y, rtau), b.y));
                o.z = f2ord(__fadd_rn(__fmul_rn(a.z, rtau), b.z));
                o.w = f2ord(__fadd_rn(__fmul_rn(a.w, rtau), b.w));
                reinterpret_cast<uint4*>(ordp)[idx] = o;
                m = max(m, max(max(o.x, o.y), max(o.z, o.w)));
            }
        } else {
            #pragma unroll
            for (int i = 0; i < VEC_ITERS; ++i) {
                const int idx = tid + i * THREADS;
                const float4 a = reinterpret_cast<const float4*>(stg_s)[idx];
                const float4 b = reinterpret_cast<const float4*>(stg_n)[idx];
                uint4 o;
                o.x = f2ord(__fadd_rn(__fdiv_rn(a.x, tau), b.x));
                o.y = f2ord(__fadd_rn(__fdiv_rn(a.y, tau), b.y));
                o.z = f2ord(__fadd_rn(__fdiv_rn(a.z, tau), b.z));
                o.w = f2ord(__fadd_rn(__fdiv_rn(a.w, tau), b.w));
                reinterpret_cast<uint4*>(ordp)[idx] = o;
                m = max(m, max(max(o.x, o.y), max(o.z, o.w)));
            }
        }
        // 8-lane group max -> 64 group maxima
        #pragma unroll
        for (int off = 4; off > 0; off >>= 1)
            m = max(m, __shfl_down_sync(0xFFFFFFFFu, m, off, 8));
        if ((tid & 7) == 0) s_gmax[tid >> 3] = m;
        __syncthreads();        // staging fully consumed; gmax ready

        // ---- refill staging with next row NOW: copy streams through the
        //      remaining phases (bulk copies do not stop at __syncthreads) ----
        const int row_next = row_i + GRID;
        if (tid == 0 && row_next < N_NODES) {
            fence_proxy_async_cta();          // order generic reads before TMA WAR
            mbar_expect_tx(mb, 2 * ROW_BYTES);
            bulk_g2s(smem_u32(stg_s), scores + (size_t)row_next * N_NODES, ROW_BYTES, mb);
            bulk_g2s(smem_u32(stg_n), noise  + (size_t)row_next * N_NODES, ROW_BYTES, mb);
        }

        // ---- phase 2: warp 0 exact-ranks the 64 group maxima ----
        // t32 = k-th largest group max <= true k-th largest element T
        // (the top-k group maxima are k distinct elements, each >= t32).
        if (tid < 32 && k >= 1 && k <= NGROUPS) {
            const uint32_t v0 = s_gmax[tid];
            const uint32_t v1 = s_gmax[tid + 32];
            int r0 = 0, r1 = 0;
            #pragma unroll 8
            for (int j = 0; j < NGROUPS; ++j) {
                const uint32_t w = s_gmax[j];
                r0 += (w > v0) || (w == v0 && j < tid);
                r1 += (w > v1) || (w == v1 && j < tid + 32);
            }
            if (r0 == k - 1) s_t32 = v0;
            if (r1 == k - 1) s_t32 = v1;
        }
        __syncthreads();
        const uint32_t t32 = s_t32;

        // ---- phase 3: fused provisional write + candidate compaction ----
        float4* op = reinterpret_cast<float4*>(out + row);
        #pragma unroll
        for (int i = 0; i < VEC_ITERS; ++i) {
            const int idx = tid + i * THREADS;
            const uint4 o = reinterpret_cast<const uint4*>(ordp)[idx];
            float4 r;
            r.x = (o.x >= t32) ? 1.0f : 0.0f;
            r.y = (o.y >= t32) ? 1.0f : 0.0f;
            r.z = (o.z >= t32) ? 1.0f : 0.0f;
            r.w = (o.w >= t32) ? 1.0f : 0.0f;
            __stcs(&op[idx], r);               // evict-first: pure write stream
            const uint32_t j = (uint32_t)idx * 4;
            if (o.x >= t32) { int p = atomicAdd(&s_ncand, 1); if (p < CAND_MAX) s_ckey[p] = make_key(o.x, j + 0); }
            if (o.y >= t32) { int p = atomicAdd(&s_ncand, 1); if (p < CAND_MAX) s_ckey[p] = make_key(o.y, j + 1); }
            if (o.z >= t32) { int p = atomicAdd(&s_ncand, 1); if (p < CAND_MAX) s_ckey[p] = make_key(o.z, j + 2); }
            if (o.w >= t32) { int p = atomicAdd(&s_ncand, 1); if (p < CAND_MAX) s_ckey[p] = make_key(o.w, j + 3); }
        }
        __syncthreads();
        const int nc = s_ncand;

        if (nc <= CAND_MAX) {
            // ---- phase 4: O(nc^2) exact rank over candidates (nc ~ k) ----
            // All true top-k have ord >= T >= t32, so they are candidates;
            // keys are unique, so (rank < k) selects exactly the global top-k.
            for (int c = tid; c < nc; c += THREADS) {
                const unsigned long long key = s_ckey[c];
                int rank = 0;
                for (int t = 0; t < nc; ++t)
                    rank += (s_ckey[t] > key);
                const uint32_t j = (uint32_t)(N_NODES - 1) - (uint32_t)(key & 0xFFFFu);
                out[row + j] = (rank < k) ? 1.0f : 0.0f;
            }
        } else {
            // ---- fallback (adversarial inputs only): exact 48-bit radix ----
            // Uses ordp only (staging may be mid-refill; never read here).
            if (tid == 0) { s_prefix = 0ull; s_krem = k; }
            for (int d = 0; d < 6; ++d) {
                if (tid < NBINS) s_hist[tid] = 0;
                __syncthreads();
                const unsigned long long pre = s_prefix;
                const int shd = 40 - 8 * d, shp = 48 - 8 * d;
                for (int jj = tid; jj < N_NODES; jj += THREADS) {
                    const unsigned long long key = make_key(ordp[jj], (uint32_t)jj);
                    if (d == 0 || (key >> shp) == pre)
                        atomicAdd(&s_hist[(uint32_t)(key >> shd) & 0xFFu], 1u);
                }
                __syncthreads();
                if (tid < 32) scan_pick(s_hist, s_cum, &s_prefix, &s_krem);
                __syncthreads();
            }
            const unsigned long long thr = s_prefix;
            for (int jj = tid; jj < N_NODES; jj += THREADS)
                out[row + jj] = (make_key(ordp[jj], (uint32_t)jj) >= thr) ? 1.0f : 0.0f;
        }
        __syncthreads();       // protect s_ckey / s_ncand / s_gmax / ordp reuse
    }
}

extern "C" void kernel_launch(void* const* d_in, const int* in_sizes, int n_in,
                              void* d_out, int out_size) {
    (void)in_sizes; (void)n_in; (void)out_size;
    const float* scores = (const float*)d_in[0];
    const float* noise  = (const float*)d_in[1];
    const float* tau    = (const float*)d_in[2];
    const int*   k      = (const int*)d_in[3];
    float* out = (float*)d_out;
    cudaFuncSetAttribute(st_subset_sampler_kernel,
                         cudaFuncAttributeMaxDynamicSharedMemorySize, DYN_SMEM);
    st_subset_sampler_kernel<<<GRID, THREADS, DYN_SMEM>>>(scores, noise, tau, k, out);
}

// round 12
// speedup vs baseline: 1.5170x; 1.1182x over previous
#include <cuda_runtime.h>
#include <cstdint>

#define N_NODES   8192
#define THREADS   512
#define GRID      444              // ~3 CTAs/SM; work-stealing absorbs SM-count delta
#define NBINS     256
#define CAND_MAX  512
#define NGROUPS   64               // 8-lane group maxima (512 thr / 8)
#define VEC_ITERS (N_NODES / 4 / THREADS)   // 4 float4 per thread
#define ROW_BYTES (N_NODES * 4)             // 32 KB per stream
#define DYN_SMEM  (2 * N_NODES * 4)         // 64 KB: staging scores | noise

__device__ unsigned g_row_ctr = GRID;   // next row to steal (module-load init)
__device__ unsigned g_done    = 0;      // finished-CTA count (self-reset)

// Monotonic float -> uint mapping (larger float => larger uint). No NaNs in inputs.
__device__ __forceinline__ uint32_t f2ord(float f) {
    uint32_t u = __float_as_uint(f);
    return u ^ ((uint32_t)((int32_t)u >> 31) | 0x80000000u);
}

// Unique 48-bit total-order key: ties in value resolve to the smaller index
// (matching jax.lax.top_k).
__device__ __forceinline__ unsigned long long make_key(uint32_t ord, uint32_t j) {
    return ((unsigned long long)ord << 16) | (unsigned)(N_NODES - 1 - j);
}

__device__ __forceinline__ uint32_t smem_u32(const void* p) {
    return (uint32_t)__cvta_generic_to_shared(p);
}
__device__ __forceinline__ void mbar_init(uint32_t a, uint32_t cnt) {
    asm volatile("mbarrier.init.shared.b64 [%0], %1;" :: "r"(a), "r"(cnt) : "memory");
}
__device__ __forceinline__ void mbar_expect_tx(uint32_t a, uint32_t bytes) {
    asm volatile("mbarrier.arrive.expect_tx.shared.b64 _, [%0], %1;"
                 :: "r"(a), "r"(bytes) : "memory");
}
__device__ __forceinline__ void mbar_wait(uint32_t mbar, uint32_t parity) {
    uint32_t done;
    asm volatile(
        "{\n\t.reg .pred p;\n\t"
        "mbarrier.try_wait.parity.acquire.cta.shared::cta.b64 p, [%1], %2;\n\t"
        "selp.b32 %0, 1, 0, p;\n\t}"
        : "=r"(done) : "r"(mbar), "r"(parity) : "memory");
    if (!done) {
        asm volatile(
            "{\n\t.reg .pred P1;\n\t"
            "WAIT_LOOP_%=:\n\t"
            "mbarrier.try_wait.parity.acquire.cta.shared::cta.b64 P1, [%0], %1, 0x989680;\n\t"
            "@P1 bra.uni WAIT_DONE_%=;\n\t"
            "bra.uni WAIT_LOOP_%=;\n\t"
            "WAIT_DONE_%=:\n\t}"
            :: "r"(mbar), "r"(parity) : "memory");
    }
}
__device__ __forceinline__ void bulk_g2s(uint32_t dst, const void* src,
                                         uint32_t bytes, uint32_t mbar) {
    asm volatile(
        "cp.async.bulk.shared::cluster.global.mbarrier::complete_tx::bytes "
        "[%0], [%1], %2, [%3];"
        :: "r"(dst), "l"(src), "r"(bytes), "r"(mbar) : "memory");
}
__device__ __forceinline__ void fence_proxy_async_cta() {
    asm volatile("fence.proxy.async.shared::cta;" ::: "memory");
}

// Fallback-only: suffix-sum a 256-bin histogram, pick bin holding krem-th largest.
__device__ __forceinline__ void scan_pick(const uint32_t* hist,
                                          volatile uint32_t* s_cum,
                                          unsigned long long* s_prefix,
                                          int* s_krem)
{
    const int lane = threadIdx.x;           // caller guarantees tid < 32
    uint32_t h[8], suf[8];
    #pragma unroll
    for (int j = 0; j < 8; ++j) h[j] = hist[lane * 8 + j];
    uint32_t acc = 0;
    #pragma unroll
    for (int j = 7; j >= 0; --j) { acc += h[j]; suf[j] = acc; }
    uint32_t run = acc;
    #pragma unroll
    for (int off = 1; off < 32; off <<= 1) {
        uint32_t v = __shfl_down_sync(0xFFFFFFFFu, run, off);
        if (lane + off < 32) run += v;
    }
    const uint32_t above = run - acc;
    #pragma unroll
    for (int j = 0; j < 8; ++j) s_cum[lane * 8 + j] = above + suf[j];
    if (lane == 0) s_cum[NBINS] = 0;
    __syncwarp();
    const uint32_t krem = (uint32_t)(*s_krem);
    #pragma unroll
    for (int j = 0; j < 8; ++j) {
        const int b = lane * 8 + j;
        const uint32_t ge = s_cum[b];
        const uint32_t gt = s_cum[b + 1];
        if (ge >= krem && gt < krem) {
            *s_prefix = (*s_prefix << 8) | (unsigned long long)(uint32_t)b;
            *s_krem   = (int)(krem - gt);
        }
    }
}

extern __shared__ float sbuf[];   // [scores 8192 | noise 8192]; ord overwrites scores

__global__ __launch_bounds__(THREADS, 3)
void st_subset_sampler_kernel(const float* __restrict__ scores,
                              const float* __restrict__ noise,
                              const float* __restrict__ tau_p,
                              const int*   __restrict__ k_p,
                              float* __restrict__ out)
{
    __shared__ uint32_t s_gmax[NGROUPS];
    __shared__ unsigned long long s_ckey[CAND_MAX];   // 4 KB candidate keys
    __shared__ int      s_ncand;
    __shared__ uint32_t s_t32;
    __shared__ int      s_next;
    __shared__ alignas(8) unsigned long long s_mb[2]; // mbar per stream: [s, n]
    // fallback-only state
    __shared__ uint32_t s_hist[NBINS];
    __shared__ uint32_t s_cum[NBINS + 1];
    __shared__ unsigned long long s_prefix;
    __shared__ int      s_krem;

    const int tid = threadIdx.x;
    const float tau = __ldg(tau_p);
    const int   k   = __ldg(k_p);

    // Power-of-two tau => a*(1/tau) is EXACT (exponent shift), so a single
    // FFMA(a, rtau, b) rounds once on the add only == fadd_rn(a/tau, b) ==
    // the reference bit-for-bit. Otherwise exact fdiv + fadd fallback.
    const uint32_t tb = __float_as_uint(tau);
    const bool pow2 = ((tb & 0x007FFFFFu) == 0u) &&
                      ((tb & 0x7F800000u) != 0u) &&
                      ((tb & 0x7F800000u) != 0x7F800000u);
    const float rtau = __frcp_rn(tau);

    float*    stg_s = sbuf;                 // raw scores; ord written in place
    float*    stg_n = sbuf + N_NODES;       // raw noise
    uint32_t* ordp  = reinterpret_cast<uint32_t*>(stg_s);
    const uint32_t mbs = smem_u32(&s_mb[0]);
    const uint32_t mbn = smem_u32(&s_mb[1]);

    // ---- prologue: init barriers, start copies for the first (static) row ----
    int row_i = blockIdx.x;
    if (tid == 0) {
        mbar_init(mbs, 1);
        mbar_init(mbn, 1);
        fence_proxy_async_cta();            // init visible to async proxy
        mbar_expect_tx(mbs, ROW_BYTES);
        bulk_g2s(smem_u32(stg_s), scores + (size_t)row_i * N_NODES, ROW_BYTES, mbs);
        mbar_expect_tx(mbn, ROW_BYTES);
        bulk_g2s(smem_u32(stg_n), noise  + (size_t)row_i * N_NODES, ROW_BYTES, mbn);
    }
    __syncthreads();

    uint32_t par = 0;
    while (row_i < N_NODES) {
        const size_t row = (size_t)row_i * N_NODES;

        if (tid == 0) {
            s_ncand = 0; s_t32 = 0;
            s_next = (int)atomicAdd(&g_row_ctr, 1u);   // ATOMG hides under wait
        }
        mbar_wait(mbs, par);                // both streams of this row resident
        mbar_wait(mbn, par);
        par ^= 1u;

        // ---- phase 1: convert staging -> ord IN PLACE over scores buffer ----
        uint32_t m = 0;
        if (pow2) {
            #pragma unroll
            for (int i = 0; i < VEC_ITERS; ++i) {
                const int idx = tid + i * THREADS;
                const float4 a = reinterpret_cast<const float4*>(stg_s)[idx];
                const float4 b = reinterpret_cast<const float4*>(stg_n)[idx];
                uint4 o;
                o.x = f2ord(__fmaf_rn(a.x, rtau, b.x));
                o.y = f2ord(__fmaf_rn(a.y, rtau, b.y));
                o.z = f2ord(__fmaf_rn(a.z, rtau, b.z));
                o.w = f2ord(__fmaf_rn(a.w, rtau, b.w));
                reinterpret_cast<uint4*>(ordp)[idx] = o;
                m = max(m, max(max(o.x, o.y), max(o.z, o.w)));
            }
        } else {
            #pragma unroll
            for (int i = 0; i < VEC_ITERS; ++i) {
                const int idx = tid + i * THREADS;
                const float4 a = reinterpret_cast<const float4*>(stg_s)[idx];
                const float4 b = reinterpret_cast<const float4*>(stg_n)[idx];
                uint4 o;
                o.x = f2ord(__fadd_rn(__fdiv_rn(a.x, tau), b.x));
                o.y = f2ord(__fadd_rn(__fdiv_rn(a.y, tau), b.y));
                o.z = f2ord(__fadd_rn(__fdiv_rn(a.z, tau), b.z));
                o.w = f2ord(__fadd_rn(__fdiv_rn(a.w, tau), b.w));
                reinterpret_cast<uint4*>(ordp)[idx] = o;
                m = max(m, max(max(o.x, o.y), max(o.z, o.w)));
            }
        }
        // 8-lane group max -> 64 group maxima
        #pragma unroll
        for (int off = 4; off > 0; off >>= 1)
            m = max(m, __shfl_down_sync(0xFFFFFFFFu, m, off, 8));
        if ((tid & 7) == 0) s_gmax[tid >> 3] = m;
        __syncthreads();        // noise staging consumed; gmax + s_next ready

        const int row_next = s_next;

        // ---- refill NOISE now: streams in background through phases 2-4 ----
        if (tid == 0 && row_next < N_NODES) {
            fence_proxy_async_cta();          // order LDS reads before TMA WAR
            mbar_expect_tx(mbn, ROW_BYTES);
            bulk_g2s(smem_u32(stg_n), noise + (size_t)row_next * N_NODES, ROW_BYTES, mbn);
        }

        // ---- phase 2: warp 0 exact-ranks the 64 group maxima ----
        // t32 = k-th largest group max <= true k-th largest element T
        // (the top-k group maxima are k distinct elements, each >= t32).
        if (tid < 32 && k >= 1 && k <= NGROUPS) {
            const uint32_t v0 = s_gmax[tid];
            const uint32_t v1 = s_gmax[tid + 32];
            int r0 = 0, r1 = 0;
            #pragma unroll 8
            for (int j = 0; j < NGROUPS; ++j) {
                const uint32_t w = s_gmax[j];
                r0 += (w > v0) || (w == v0 && j < tid);
                r1 += (w > v1) || (w == v1 && j < tid + 32);
            }
            if (r0 == k - 1) s_t32 = v0;
            if (r1 == k - 1) s_t32 = v1;
        }
        __syncthreads();
        const uint32_t t32 = s_t32;

        // ---- phase 3: fused provisional write + candidate compaction ----
        float4* op = reinterpret_cast<float4*>(out + row);
        #pragma unroll
        for (int i = 0; i < VEC_ITERS; ++i) {
            const int idx = tid + i * THREADS;
            const uint4 o = reinterpret_cast<const uint4*>(ordp)[idx];
            float4 r;
            r.x = (o.x >= t32) ? 1.0f : 0.0f;
            r.y = (o.y >= t32) ? 1.0f : 0.0f;
            r.z = (o.z >= t32) ? 1.0f : 0.0f;
            r.w = (o.w >= t32) ? 1.0f : 0.0f;
            __stcs(&op[idx], r);               // evict-first: pure write stream
            const uint32_t j = (uint32_t)idx * 4;
            if (o.x >= t32) { int p = atomicAdd(&s_ncand, 1); if (p < CAND_MAX) s_ckey[p] = make_key(o.x, j + 0); }
            if (o.y >= t32) { int p = atomicAdd(&s_ncand, 1); if (p < CAND_MAX) s_ckey[p] = make_key(o.y, j + 1); }
            if (o.z >= t32) { int p = atomicAdd(&s_ncand, 1); if (p < CAND_MAX) s_ckey[p] = make_key(o.z, j + 2); }
            if (o.w >= t32) { int p = atomicAdd(&s_ncand, 1); if (p < CAND_MAX) s_ckey[p] = make_key(o.w, j + 3); }
        }
        __syncthreads();
        const int nc = s_ncand;

        if (nc <= CAND_MAX) {
            // ---- ord buffer dead: refill SCORES now; phase 4 uses s_ckey only ----
            if (tid == 0 && row_next < N_NODES) {
                fence_proxy_async_cta();
                mbar_expect_tx(mbs, ROW_BYTES);
                bulk_g2s(smem_u32(stg_s), scores + (size_t)row_next * N_NODES, ROW_BYTES, mbs);
            }
            // ---- phase 4: O(nc^2) exact rank over candidates (nc ~ k) ----
            // All true top-k have ord >= T >= t32, so they are candidates;
            // keys are unique, so (rank < k) selects exactly the global top-k.
            for (int c = tid; c < nc; c += THREADS) {
                const unsigned long long key = s_ckey[c];
                int rank = 0;
                for (int t = 0; t < nc; ++t)
                    rank += (s_ckey[t] > key);
                const uint32_t j = (uint32_t)(N_NODES - 1) - (uint32_t)(key & 0xFFFFu);
                out[row + j] = (rank < k) ? 1.0f : 0.0f;
            }
        } else {
            // ---- fallback (adversarial inputs only): exact 48-bit radix ----
            // Reads ordp throughout, so the scores refill waits until the end.
            if (tid == 0) { s_prefix = 0ull; s_krem = k; }
            for (int d = 0; d < 6; ++d) {
                if (tid < NBINS) s_hist[tid] = 0;
                __syncthreads();
                const unsigned long long pre = s_prefix;
                const int shd = 40 - 8 * d, shp = 48 - 8 * d;
                for (int jj = tid; jj < N_NODES; jj += THREADS) {
                    const unsigned long long key = make_key(ordp[jj], (uint32_t)jj);
                    if (d == 0 || (key >> shp) == pre)
                        atomicAdd(&s_hist[(uint32_t)(key >> shd) & 0xFFu], 1u);
                }
                __syncthreads();
                if (tid < 32) scan_pick(s_hist, s_cum, &s_prefix, &s_krem);
                __syncthreads();
            }
            const unsigned long long thr = s_prefix;
            for (int jj = tid; jj < N_NODES; jj += THREADS)
                out[row + jj] = (make_key(ordp[jj], (uint32_t)jj) >= thr) ? 1.0f : 0.0f;
            __syncthreads();
            if (tid == 0 && row_next < N_NODES) {
                fence_proxy_async_cta();
                mbar_expect_tx(mbs, ROW_BYTES);
                bulk_g2s(smem_u32(stg_s), scores + (size_t)row_next * N_NODES, ROW_BYTES, mbs);
            }
        }
        __syncthreads();       // protect s_ckey / s_ncand / s_gmax / s_next reuse
        row_i = row_next;
    }

    // ---- self-reset of scheduler state for graph replay determinism ----
    if (tid == 0) {
        __threadfence();
        if (atomicAdd(&g_done, 1u) == gridDim.x - 1) {  // last CTA; counter drained
            g_row_ctr = GRID;
            __threadfence();
            atomicExch(&g_done, 0u);
        }
    }
}

extern "C" void kernel_launch(void* const* d_in, const int* in_sizes, int n_in,
                              void* d_out, int out_size) {
    (void)in_sizes; (void)n_in; (void)out_size;
    const float* scores = (const float*)d_in[0];
    const float* noise  = (const float*)d_in[1];
    const float* tau    = (const float*)d_in[2];
    const int*   k      = (const int*)d_in[3];
    float* out = (float*)d_out;
    cudaFuncSetAttribute(st_subset_sampler_kernel,
                         cudaFuncAttributeMaxDynamicSharedMemorySize, DYN_SMEM);
    st_subset_sampler_kernel<<<GRID, THREADS, DYN_SMEM>>>(scores, noise, tau, k, out);
}